// round 8
// baseline (speedup 1.0000x reference)
#include <cuda_runtime.h>
#include <cuda_fp16.h>
#include <math.h>

// Sinkhorn distance: B=16, Lx=Ly=1024, D=256, eps=0.1, 50 iters.
// Log-domain in log2 units: lk2 = -cost*(10/ln2), log_mu2 = log_nu2 = -10.
// Cost stored fp16 TWICE (row-major + transposed); dual vector staged in
// shared with a swizzle giving conflict-free lane-contiguous LDS.64.
// The 16 batches are independent: 512 persistent blocks = 16 groups of 32,
// each group iterates its own batch with a private group barrier (no global
// straggler coupling). Transport is fused into the 50th col pass:
//   per column j:  contrib = 2^-10 * (sum_i 2^(a_i - m) c_i) / (sum_i 2^(a_i - m))
// One global barrier before the final reduction.

#define BATCH 16
#define LSEQ  1024
#define DDIM  256
#define K2C   14.426950408889634f   // 10 / ln(2)
#define NBLK  512
#define NTHR  256
#define NGRP  32                     // blocks per batch group

__device__ __half g_ch[(size_t)BATCH * LSEQ * LSEQ];  // 32 MB row-major cost
__device__ __half g_ct[(size_t)BATCH * LSEQ * LSEQ];  // 32 MB transposed cost
__device__ float g_x2[BATCH * LSEQ];
__device__ float g_y2[BATCH * LSEQ];
__device__ float g_lu[BATCH * LSEQ];
__device__ float g_lv[BATCH * LSEQ];
__device__ float g_part[NBLK];
__device__ unsigned g_bar_cnt = 0;
__device__ unsigned g_bar_gen = 0;

struct __align__(128) GroupBar { unsigned cnt; unsigned gen; unsigned pad[30]; };
__device__ GroupBar g_gbar[BATCH];

static __device__ __forceinline__ float ex2f(float x) {
    float r; asm("ex2.approx.ftz.f32 %0, %1;" : "=f"(r) : "f"(x)); return r;
}
static __device__ __forceinline__ float lg2f(float x) {
    float r; asm("lg2.approx.ftz.f32 %0, %1;" : "=f"(r) : "f"(x)); return r;
}

typedef unsigned long long ull;
static __device__ __forceinline__ ull pack2(float lo, float hi) {
    ull r; asm("mov.b64 %0, {%1, %2};" : "=l"(r) : "f"(lo), "f"(hi)); return r;
}
static __device__ __forceinline__ float2 unpack2(ull v) {
    float2 r; asm("mov.b64 {%0, %1}, %2;" : "=f"(r.x), "=f"(r.y) : "l"(v)); return r;
}
static __device__ __forceinline__ void ffma2(ull& d, ull a, ull b) {
    asm("fma.rn.f32x2 %0, %1, %2, %0;" : "+l"(d) : "l"(a), "l"(b));
}

// Group barrier: 32 blocks of one batch. Sense-reversing; own cache line.
static __device__ __forceinline__ void group_barrier(int grp) {
    __syncthreads();
    if (threadIdx.x == 0) {
        __threadfence();
        unsigned gen = *(volatile unsigned*)&g_gbar[grp].gen;
        unsigned prev = atomicAdd(&g_gbar[grp].cnt, 1u);
        if (prev == NGRP - 1) {
            g_gbar[grp].cnt = 0;
            __threadfence();
            *(volatile unsigned*)&g_gbar[grp].gen = gen + 1;
        } else {
            while (*(volatile unsigned*)&g_gbar[grp].gen == gen) { __nanosleep(16); }
        }
        __threadfence();
    }
    __syncthreads();
}

// Global barrier over all 512 blocks (used once, before final reduce).
static __device__ __forceinline__ void grid_barrier() {
    __syncthreads();
    if (threadIdx.x == 0) {
        __threadfence();
        unsigned gen = *(volatile unsigned*)&g_bar_gen;
        unsigned prev = atomicAdd(&g_bar_cnt, 1u);
        if (prev == NBLK - 1) {
            g_bar_cnt = 0;
            __threadfence();
            *(volatile unsigned*)&g_bar_gen = gen + 1;
        } else {
            while (*(volatile unsigned*)&g_bar_gen == gen) { __nanosleep(32); }
        }
        __threadfence();
    }
    __syncthreads();
}

// ---------------------------------------------------------------------------
// Kernel 1: row sums of squares; zero-init log_u / log_v.
// ---------------------------------------------------------------------------
__global__ __launch_bounds__(256) void sumsq_kernel(const float* __restrict__ x,
                                                    const float* __restrict__ y) {
    int warp = (blockIdx.x * 256 + threadIdx.x) >> 5;
    int lane = threadIdx.x & 31;
    int isx = (warp < BATCH * LSEQ);
    int r = isx ? warp : warp - BATCH * LSEQ;
    const float* src = isx ? x : y;
    const float4* p = (const float4*)(src + (size_t)r * DDIM);
    float s = 0.f;
#pragma unroll
    for (int t = 0; t < 2; t++) {
        float4 v = p[lane + 32 * t];
        s += v.x * v.x + v.y * v.y + v.z * v.z + v.w * v.w;
    }
#pragma unroll
    for (int o = 16; o; o >>= 1) s += __shfl_xor_sync(0xffffffffu, s, o);
    if (lane == 0) {
        if (isx) { g_x2[r] = s; g_lu[r] = 0.f; }
        else     { g_y2[r] = s; g_lv[r] = 0.f; }
    }
}

// ---------------------------------------------------------------------------
// Kernel 2: batched cost GEMM.  cost = sqrt(max(x2 + y2 - 2*x@y^T, 0)).
// 128x128 tile, BK=8, 256 threads, 8x8 microtile, packed f32x2 FMAs.
// Epilogue writes fp16 cost row-major AND transposed.
// ---------------------------------------------------------------------------
__global__ __launch_bounds__(256, 2) void cost_kernel(const float* __restrict__ x,
                                                      const float* __restrict__ y) {
    __shared__ __align__(16) float As[8][128];
    __shared__ __align__(16) float Bs[8][128];
    int b = blockIdx.z;
    int i0 = blockIdx.y * 128;
    int j0 = blockIdx.x * 128;
    int tid = threadIdx.x;
    int tx = tid & 15, ty = tid >> 4;
    const float* xb = x + (size_t)b * LSEQ * DDIM;
    const float* yb = y + (size_t)b * LSEQ * DDIM;
    int lr = tid >> 1;
    int lc = (tid & 1) * 4;

    ull acc[8][4];
#pragma unroll
    for (int ri = 0; ri < 8; ri++)
#pragma unroll
        for (int cj = 0; cj < 4; cj++) acc[ri][cj] = 0ull;

    for (int k0 = 0; k0 < DDIM; k0 += 8) {
        float4 av = *(const float4*)(xb + (size_t)(i0 + lr) * DDIM + k0 + lc);
        float4 bv = *(const float4*)(yb + (size_t)(j0 + lr) * DDIM + k0 + lc);
        __syncthreads();
        As[lc + 0][lr] = av.x; As[lc + 1][lr] = av.y;
        As[lc + 2][lr] = av.z; As[lc + 3][lr] = av.w;
        Bs[lc + 0][lr] = bv.x; Bs[lc + 1][lr] = bv.y;
        Bs[lc + 2][lr] = bv.z; Bs[lc + 3][lr] = bv.w;
        __syncthreads();
#pragma unroll
        for (int kk = 0; kk < 8; kk++) {
            float4 a0 = *(const float4*)&As[kk][ty * 8];
            float4 a1 = *(const float4*)&As[kk][ty * 8 + 4];
            float4 b0 = *(const float4*)&Bs[kk][tx * 8];
            float4 b1 = *(const float4*)&Bs[kk][tx * 8 + 4];
            ull bp[4];
            bp[0] = pack2(b0.x, b0.y); bp[1] = pack2(b0.z, b0.w);
            bp[2] = pack2(b1.x, b1.y); bp[3] = pack2(b1.z, b1.w);
            float a[8] = {a0.x, a0.y, a0.z, a0.w, a1.x, a1.y, a1.z, a1.w};
#pragma unroll
            for (int ri = 0; ri < 8; ri++) {
                ull ap = pack2(a[ri], a[ri]);
#pragma unroll
                for (int cj = 0; cj < 4; cj++) ffma2(acc[ri][cj], ap, bp[cj]);
            }
        }
    }

    float x2r[8], y2c[8];
#pragma unroll
    for (int ri = 0; ri < 8; ri++) x2r[ri] = g_x2[b * LSEQ + i0 + ty * 8 + ri];
#pragma unroll
    for (int c = 0; c < 8; c++)    y2c[c]  = g_y2[b * LSEQ + j0 + tx * 8 + c];

    __half hout[8][8];
#pragma unroll
    for (int ri = 0; ri < 8; ri++) {
        float out[8];
#pragma unroll
        for (int cj = 0; cj < 4; cj++) {
            float2 u = unpack2(acc[ri][cj]);
            out[2 * cj] = u.x; out[2 * cj + 1] = u.y;
        }
#pragma unroll
        for (int c = 0; c < 8; c++) {
            float d2 = x2r[ri] + y2c[c] - 2.f * out[c];
            hout[ri][c] = __float2half_rn(sqrtf(fmaxf(d2, 0.f)));
        }
        __half* dst = g_ch + ((size_t)b << 20) + (size_t)(i0 + ty * 8 + ri) * LSEQ + j0 + tx * 8;
        *(uint4*)dst = *(uint4*)&hout[ri][0];
    }
#pragma unroll
    for (int c = 0; c < 8; c++) {
        __half tcol[8];
#pragma unroll
        for (int ri = 0; ri < 8; ri++) tcol[ri] = hout[ri][c];
        __half* dst = g_ct + ((size_t)b << 20) + (size_t)(j0 + tx * 8 + c) * LSEQ + i0 + ty * 8;
        *(uint4*)dst = *(uint4*)&tcol[0];
    }
}

// ---------------------------------------------------------------------------
// Shared-vec swizzle: slv2[(j&3)*128 + (j>>2)] = float2 pair j (elems 2j,2j+1).
// Chunk ci (8 halfs = elems 8ci..8ci+7) pairs with slv2[e*128+ci], e=0..3 —
// lane-contiguous LDS.64, conflict-free.
// ---------------------------------------------------------------------------
static __device__ __forceinline__ void stage_vec(float2* slv2, const float* vec) {
#pragma unroll
    for (int j = threadIdx.x; j < 512; j += NTHR) {
        float2 p = __ldcg(((const float2*)vec) + j);
        slv2[(j & 3) * 128 + (j >> 2)] = p;
    }
}

// LSE over one 1024-long fp16 line; vec from swizzled shared. Warp-collective.
static __device__ __forceinline__ float warp_line_lse(const uint4* __restrict__ line,
                                                      const float2* __restrict__ slv2,
                                                      int lane) {
    float m = -1e30f, s = 0.f;
#pragma unroll
    for (int t = 0; t < 2; t++) {
        float a[16];
#pragma unroll
        for (int h = 0; h < 2; h++) {
            int ci = lane + 32 * (2 * t + h);
            uint4 q = line[ci];
            float2 p0 = slv2[ci];
            float2 p1 = slv2[128 + ci];
            float2 p2 = slv2[256 + ci];
            float2 p3 = slv2[384 + ci];
            const __half2* hp = (const __half2*)&q;
            float2 f0 = __half22float2(hp[0]);
            float2 f1 = __half22float2(hp[1]);
            float2 f2 = __half22float2(hp[2]);
            float2 f3 = __half22float2(hp[3]);
            float* A = a + 8 * h;
            A[0] = fmaf(f0.x, -K2C, p0.x); A[1] = fmaf(f0.y, -K2C, p0.y);
            A[2] = fmaf(f1.x, -K2C, p1.x); A[3] = fmaf(f1.y, -K2C, p1.y);
            A[4] = fmaf(f2.x, -K2C, p2.x); A[5] = fmaf(f2.y, -K2C, p2.y);
            A[6] = fmaf(f3.x, -K2C, p3.x); A[7] = fmaf(f3.y, -K2C, p3.y);
        }
        float cm = a[0];
#pragma unroll
        for (int e = 1; e < 16; e++) cm = fmaxf(cm, a[e]);
        float M = fmaxf(m, cm);
        s *= ex2f(m - M);
#pragma unroll
        for (int e = 0; e < 16; e++) s += ex2f(a[e] - M);
        m = M;
    }
#pragma unroll
    for (int o = 16; o; o >>= 1) {
        float m2 = __shfl_xor_sync(0xffffffffu, m, o);
        float s2 = __shfl_xor_sync(0xffffffffu, s, o);
        float M = fmaxf(m, m2);
        s = s * ex2f(m - M) + s2 * ex2f(m2 - M);
        m = M;
    }
    return -10.f - (m + lg2f(s));
}

// Final fused col pass: LSE + transport t-sum over one line of C^T.
// Returns (per lane 0) the column's transport contribution t/s (x 2^-10 later).
static __device__ __forceinline__ float warp_line_transport(const uint4* __restrict__ line,
                                                            const float2* __restrict__ slv2,
                                                            int lane) {
    float m = -1e30f, s = 0.f, tt = 0.f;
#pragma unroll
    for (int t = 0; t < 2; t++) {
        float a[16], cv[16];
#pragma unroll
        for (int h = 0; h < 2; h++) {
            int ci = lane + 32 * (2 * t + h);
            uint4 q = line[ci];
            float2 p0 = slv2[ci];
            float2 p1 = slv2[128 + ci];
            float2 p2 = slv2[256 + ci];
            float2 p3 = slv2[384 + ci];
            const __half2* hp = (const __half2*)&q;
            float2 f0 = __half22float2(hp[0]);
            float2 f1 = __half22float2(hp[1]);
            float2 f2 = __half22float2(hp[2]);
            float2 f3 = __half22float2(hp[3]);
            float* A = a + 8 * h;
            float* C = cv + 8 * h;
            C[0] = f0.x; C[1] = f0.y; C[2] = f1.x; C[3] = f1.y;
            C[4] = f2.x; C[5] = f2.y; C[6] = f3.x; C[7] = f3.y;
            A[0] = fmaf(f0.x, -K2C, p0.x); A[1] = fmaf(f0.y, -K2C, p0.y);
            A[2] = fmaf(f1.x, -K2C, p1.x); A[3] = fmaf(f1.y, -K2C, p1.y);
            A[4] = fmaf(f2.x, -K2C, p2.x); A[5] = fmaf(f2.y, -K2C, p2.y);
            A[6] = fmaf(f3.x, -K2C, p3.x); A[7] = fmaf(f3.y, -K2C, p3.y);
        }
        float cm = a[0];
#pragma unroll
        for (int e = 1; e < 16; e++) cm = fmaxf(cm, a[e]);
        float M = fmaxf(m, cm);
        float sc = ex2f(m - M);
        s *= sc; tt *= sc;
#pragma unroll
        for (int e = 0; e < 16; e++) {
            float w = ex2f(a[e] - M);
            s += w;
            tt = fmaf(w, cv[e], tt);
        }
        m = M;
    }
#pragma unroll
    for (int o = 16; o; o >>= 1) {
        float m2 = __shfl_xor_sync(0xffffffffu, m, o);
        float s2 = __shfl_xor_sync(0xffffffffu, s, o);
        float t2 = __shfl_xor_sync(0xffffffffu, tt, o);
        float M = fmaxf(m, m2);
        float e1 = ex2f(m - M), e2 = ex2f(m2 - M);
        s = s * e1 + s2 * e2;
        tt = tt * e1 + t2 * e2;
        m = M;
    }
    return tt / s;   // valid on all lanes after full butterfly
}

// ---------------------------------------------------------------------------
// Kernel 3: persistent Sinkhorn. 16 independent groups of 32 blocks, one per
// batch; group-local barriers between half-sweeps. 50th col pass fused with
// transport. One global barrier before the final reduce.
// ---------------------------------------------------------------------------
__global__ __launch_bounds__(NTHR, 4) void sinkhorn_persist(float* __restrict__ out) {
    __shared__ __align__(16) float2 slv2[512];
    __shared__ float smx[256];
    __shared__ float wsum[8];

    int tid = threadIdx.x;
    int w = tid >> 5;
    int lane = tid & 31;
    int b = blockIdx.x >> 5;                    // batch / group id
    int lbase = (blockIdx.x & 31) * 32;         // first line in group
    const float* lvb = g_lv + (b << 10);
    const float* lub = g_lu + (b << 10);

    for (int it = 0; it < 50; ++it) {
        // row pass: log_u[r] = -10 - LSE2_j(lv[j] - K2*C[r,j])
        stage_vec(slv2, lvb);
        __syncthreads();
#pragma unroll 1
        for (int k = 0; k < 4; ++k) {
            int row = (b << 10) + lbase + w * 4 + k;
            float r = warp_line_lse((const uint4*)(g_ch + ((size_t)row << 10)), slv2, lane);
            if (lane == 0) g_lu[row] = r;
        }
        group_barrier(b);
        if (it < 49) {
            // col pass: log_v[c] = -10 - LSE2_i(lu[i] - K2*C[i,c])  (via C^T)
            stage_vec(slv2, lub);
            __syncthreads();
#pragma unroll 1
            for (int k = 0; k < 4; ++k) {
                int col = (b << 10) + lbase + w * 4 + k;
                float r = warp_line_lse((const uint4*)(g_ct + ((size_t)col << 10)), slv2, lane);
                if (lane == 0) g_lv[col] = r;
            }
            group_barrier(b);
        }
    }

    // 50th col pass fused with transport:
    // contribution of column j = 2^-10 * t_j / s_j  (lv_j never materialized)
    {
        stage_vec(slv2, lub);
        __syncthreads();
        float s = 0.f;
#pragma unroll 1
        for (int k = 0; k < 4; ++k) {
            int col = (b << 10) + lbase + w * 4 + k;
            s += warp_line_transport((const uint4*)(g_ct + ((size_t)col << 10)), slv2, lane);
        }
        // s identical across lanes (full butterfly); lane 0 records warp total
        if (lane == 0) wsum[w] = s;
        __syncthreads();
        if (tid == 0) {
            float t = 0.f;
#pragma unroll
            for (int i = 0; i < 8; i++) t += wsum[i];
            g_part[blockIdx.x] = t;
        }
    }
    grid_barrier();

    if (blockIdx.x == 0) {
        float s = 0.f;
        for (int i = tid; i < NBLK; i += 256) s += __ldcg(&g_part[i]);
        smx[tid] = s;
        __syncthreads();
        for (int o = 128; o; o >>= 1) {
            if (tid < o) smx[tid] += smx[tid + o];
            __syncthreads();
        }
        // 2^-10 from lv normalization, /16 for the batch mean
        if (tid == 0) out[0] = smx[0] * (1.f / (1024.f * 16.f));
    }
}

// ---------------------------------------------------------------------------
extern "C" void kernel_launch(void* const* d_in, const int* in_sizes, int n_in,
                              void* d_out, int out_size) {
    const float* x = (const float*)d_in[0];
    const float* y = (const float*)d_in[1];
    float* out = (float*)d_out;

    sumsq_kernel<<<4096, 256>>>(x, y);
    cost_kernel<<<dim3(8, 8, 16), 256>>>(x, y);
    sinkhorn_persist<<<NBLK, NTHR>>>(out);
}

// round 9
// speedup vs baseline: 1.5284x; 1.5284x over previous
#include <cuda_runtime.h>
#include <cuda_fp16.h>
#include <math.h>

// Sinkhorn distance: B=16, Lx=Ly=1024, D=256, eps=0.1, 50 iters.
// Log-domain in log2 units: lk2 = -cost*(10/ln2), log_mu2 = log_nu2 = -10.
// Cost stored fp16 TWICE (row-major + transposed); dual vector staged in
// shared (conflict-free swizzle). One persistent kernel, global lockstep
// barriers. Iterations 1..49 use a STALE-SHIFT LSE (M = previous iteration's
// LSE, register-resident; safe: LSE is 1-Lipschitz in sup-norm so iteration
// deltas are bounded ~50 log2 units << fp32's +-120 headroom). Iteration 0
// uses the exact-max path. 50th col pass fused with the transport sum.

#define BATCH 16
#define LSEQ  1024
#define DDIM  256
#define K2C   14.426950408889634f   // 10 / ln(2)
#define NBLK  512
#define NTHR  256

__device__ __half g_ch[(size_t)BATCH * LSEQ * LSEQ];  // 32 MB row-major cost
__device__ __half g_ct[(size_t)BATCH * LSEQ * LSEQ];  // 32 MB transposed cost
__device__ float g_x2[BATCH * LSEQ];
__device__ float g_y2[BATCH * LSEQ];
__device__ float g_lu[BATCH * LSEQ];
__device__ float g_lv[BATCH * LSEQ];
__device__ float g_part[NBLK];
__device__ unsigned g_bar_cnt = 0;
__device__ unsigned g_bar_gen = 0;

static __device__ __forceinline__ float ex2f(float x) {
    float r; asm("ex2.approx.ftz.f32 %0, %1;" : "=f"(r) : "f"(x)); return r;
}
static __device__ __forceinline__ float lg2f(float x) {
    float r; asm("lg2.approx.ftz.f32 %0, %1;" : "=f"(r) : "f"(x)); return r;
}

typedef unsigned long long ull;
static __device__ __forceinline__ ull pack2(float lo, float hi) {
    ull r; asm("mov.b64 %0, {%1, %2};" : "=l"(r) : "f"(lo), "f"(hi)); return r;
}
static __device__ __forceinline__ float2 unpack2(ull v) {
    float2 r; asm("mov.b64 {%0, %1}, %2;" : "=f"(r.x), "=f"(r.y) : "l"(v)); return r;
}
static __device__ __forceinline__ void ffma2(ull& d, ull a, ull b) {
    asm("fma.rn.f32x2 %0, %1, %2, %0;" : "+l"(d) : "l"(a), "l"(b));
}
static __device__ __forceinline__ void fadd2(ull& d, ull a) {
    asm("add.rn.f32x2 %0, %0, %1;" : "+l"(d) : "l"(a));
}
// d = a*b + c
static __device__ __forceinline__ ull ffma2v(ull a, ull b, ull c) {
    ull d;
    asm("fma.rn.f32x2 %0, %1, %2, %3;" : "=l"(d) : "l"(a), "l"(b), "l"(c));
    return d;
}

// Sense-reversing global barrier (512 blocks; launch_bounds(256,4) -> 592 slots).
static __device__ __forceinline__ void grid_barrier() {
    __syncthreads();
    if (threadIdx.x == 0) {
        __threadfence();
        unsigned gen = *(volatile unsigned*)&g_bar_gen;
        unsigned prev = atomicAdd(&g_bar_cnt, 1u);
        if (prev == NBLK - 1) {
            g_bar_cnt = 0;
            __threadfence();
            *(volatile unsigned*)&g_bar_gen = gen + 1;
        } else {
            while (*(volatile unsigned*)&g_bar_gen == gen) { __nanosleep(32); }
        }
        __threadfence();
    }
    __syncthreads();
}

// ---------------------------------------------------------------------------
// Kernel 1: row sums of squares; zero-init log_u / log_v.
// ---------------------------------------------------------------------------
__global__ __launch_bounds__(256) void sumsq_kernel(const float* __restrict__ x,
                                                    const float* __restrict__ y) {
    int warp = (blockIdx.x * 256 + threadIdx.x) >> 5;
    int lane = threadIdx.x & 31;
    int isx = (warp < BATCH * LSEQ);
    int r = isx ? warp : warp - BATCH * LSEQ;
    const float* src = isx ? x : y;
    const float4* p = (const float4*)(src + (size_t)r * DDIM);
    float s = 0.f;
#pragma unroll
    for (int t = 0; t < 2; t++) {
        float4 v = p[lane + 32 * t];
        s += v.x * v.x + v.y * v.y + v.z * v.z + v.w * v.w;
    }
#pragma unroll
    for (int o = 16; o; o >>= 1) s += __shfl_xor_sync(0xffffffffu, s, o);
    if (lane == 0) {
        if (isx) { g_x2[r] = s; g_lu[r] = 0.f; }
        else     { g_y2[r] = s; g_lv[r] = 0.f; }
    }
}

// ---------------------------------------------------------------------------
// Kernel 2: batched cost GEMM.  cost = sqrt(max(x2 + y2 - 2*x@y^T, 0)).
// ---------------------------------------------------------------------------
__global__ __launch_bounds__(256, 2) void cost_kernel(const float* __restrict__ x,
                                                      const float* __restrict__ y) {
    __shared__ __align__(16) float As[8][128];
    __shared__ __align__(16) float Bs[8][128];
    int b = blockIdx.z;
    int i0 = blockIdx.y * 128;
    int j0 = blockIdx.x * 128;
    int tid = threadIdx.x;
    int tx = tid & 15, ty = tid >> 4;
    const float* xb = x + (size_t)b * LSEQ * DDIM;
    const float* yb = y + (size_t)b * LSEQ * DDIM;
    int lr = tid >> 1;
    int lc = (tid & 1) * 4;

    ull acc[8][4];
#pragma unroll
    for (int ri = 0; ri < 8; ri++)
#pragma unroll
        for (int cj = 0; cj < 4; cj++) acc[ri][cj] = 0ull;

    for (int k0 = 0; k0 < DDIM; k0 += 8) {
        float4 av = *(const float4*)(xb + (size_t)(i0 + lr) * DDIM + k0 + lc);
        float4 bv = *(const float4*)(yb + (size_t)(j0 + lr) * DDIM + k0 + lc);
        __syncthreads();
        As[lc + 0][lr] = av.x; As[lc + 1][lr] = av.y;
        As[lc + 2][lr] = av.z; As[lc + 3][lr] = av.w;
        Bs[lc + 0][lr] = bv.x; Bs[lc + 1][lr] = bv.y;
        Bs[lc + 2][lr] = bv.z; Bs[lc + 3][lr] = bv.w;
        __syncthreads();
#pragma unroll
        for (int kk = 0; kk < 8; kk++) {
            float4 a0 = *(const float4*)&As[kk][ty * 8];
            float4 a1 = *(const float4*)&As[kk][ty * 8 + 4];
            float4 b0 = *(const float4*)&Bs[kk][tx * 8];
            float4 b1 = *(const float4*)&Bs[kk][tx * 8 + 4];
            ull bp[4];
            bp[0] = pack2(b0.x, b0.y); bp[1] = pack2(b0.z, b0.w);
            bp[2] = pack2(b1.x, b1.y); bp[3] = pack2(b1.z, b1.w);
            float a[8] = {a0.x, a0.y, a0.z, a0.w, a1.x, a1.y, a1.z, a1.w};
#pragma unroll
            for (int ri = 0; ri < 8; ri++) {
                ull ap = pack2(a[ri], a[ri]);
#pragma unroll
                for (int cj = 0; cj < 4; cj++) ffma2(acc[ri][cj], ap, bp[cj]);
            }
        }
    }

    float x2r[8], y2c[8];
#pragma unroll
    for (int ri = 0; ri < 8; ri++) x2r[ri] = g_x2[b * LSEQ + i0 + ty * 8 + ri];
#pragma unroll
    for (int c = 0; c < 8; c++)    y2c[c]  = g_y2[b * LSEQ + j0 + tx * 8 + c];

    __half hout[8][8];
#pragma unroll
    for (int ri = 0; ri < 8; ri++) {
        float out[8];
#pragma unroll
        for (int cj = 0; cj < 4; cj++) {
            float2 u = unpack2(acc[ri][cj]);
            out[2 * cj] = u.x; out[2 * cj + 1] = u.y;
        }
#pragma unroll
        for (int c = 0; c < 8; c++) {
            float d2 = x2r[ri] + y2c[c] - 2.f * out[c];
            hout[ri][c] = __float2half_rn(sqrtf(fmaxf(d2, 0.f)));
        }
        __half* dst = g_ch + ((size_t)b << 20) + (size_t)(i0 + ty * 8 + ri) * LSEQ + j0 + tx * 8;
        *(uint4*)dst = *(uint4*)&hout[ri][0];
    }
#pragma unroll
    for (int c = 0; c < 8; c++) {
        __half tcol[8];
#pragma unroll
        for (int ri = 0; ri < 8; ri++) tcol[ri] = hout[ri][c];
        __half* dst = g_ct + ((size_t)b << 20) + (size_t)(j0 + tx * 8 + c) * LSEQ + i0 + ty * 8;
        *(uint4*)dst = *(uint4*)&tcol[0];
    }
}

// ---------------------------------------------------------------------------
// Shared-vec swizzle: slv2[(j&3)*128 + (j>>2)] = float2 pair j.
// ---------------------------------------------------------------------------
static __device__ __forceinline__ void stage_vec(float2* slv2, const float* vec) {
#pragma unroll
    for (int j = threadIdx.x; j < 512; j += NTHR) {
        float2 p = __ldcg(((const float2*)vec) + j);
        slv2[(j & 3) * 128 + (j >> 2)] = p;
    }
}

// Exact-max LSE (iteration 0 only). Returns LSE on ALL lanes.
static __device__ __forceinline__ float warp_line_lse_exact(const uint4* __restrict__ line,
                                                            const float2* __restrict__ slv2,
                                                            int lane) {
    float m = -1e30f, s = 0.f;
#pragma unroll
    for (int t = 0; t < 2; t++) {
        float a[16];
#pragma unroll
        for (int h = 0; h < 2; h++) {
            int ci = lane + 32 * (2 * t + h);
            uint4 q = line[ci];
            float2 p0 = slv2[ci];
            float2 p1 = slv2[128 + ci];
            float2 p2 = slv2[256 + ci];
            float2 p3 = slv2[384 + ci];
            const __half2* hp = (const __half2*)&q;
            float2 f0 = __half22float2(hp[0]);
            float2 f1 = __half22float2(hp[1]);
            float2 f2 = __half22float2(hp[2]);
            float2 f3 = __half22float2(hp[3]);
            float* A = a + 8 * h;
            A[0] = fmaf(f0.x, -K2C, p0.x); A[1] = fmaf(f0.y, -K2C, p0.y);
            A[2] = fmaf(f1.x, -K2C, p1.x); A[3] = fmaf(f1.y, -K2C, p1.y);
            A[4] = fmaf(f2.x, -K2C, p2.x); A[5] = fmaf(f2.y, -K2C, p2.y);
            A[6] = fmaf(f3.x, -K2C, p3.x); A[7] = fmaf(f3.y, -K2C, p3.y);
        }
        float cm = a[0];
#pragma unroll
        for (int e = 1; e < 16; e++) cm = fmaxf(cm, a[e]);
        float M = fmaxf(m, cm);
        s *= ex2f(m - M);
#pragma unroll
        for (int e = 0; e < 16; e++) s += ex2f(a[e] - M);
        m = M;
    }
#pragma unroll
    for (int o = 16; o; o >>= 1) {
        float m2 = __shfl_xor_sync(0xffffffffu, m, o);
        float s2 = __shfl_xor_sync(0xffffffffu, s, o);
        float M = fmaxf(m, m2);
        s = s * ex2f(m - M) + s2 * ex2f(m2 - M);
        m = M;
    }
    return m + lg2f(s);
}

// Stale-shift LSE (iterations >= 1). Returns LSE on ALL lanes.
static __device__ __forceinline__ float warp_line_lse_shift(const uint4* __restrict__ line,
                                                            const float2* __restrict__ slv2,
                                                            int lane, float M) {
    uint4 q[4];
#pragma unroll
    for (int t = 0; t < 4; t++) q[t] = line[lane + 32 * t];
    const ull negM2 = pack2(-M, -M);
    const ull negK2 = pack2(-K2C, -K2C);
    ull s2 = 0ull;
#pragma unroll
    for (int t = 0; t < 4; t++) {
        int ci = lane + 32 * t;
        const __half2* hp = (const __half2*)&q[t];
#pragma unroll
        for (int e = 0; e < 4; e++) {
            float2 lv = slv2[e * 128 + ci];
            float2 cf = __half22float2(hp[e]);
            ull lvm2 = pack2(lv.x, lv.y);
            fadd2(lvm2, negM2);                       // lv - M
            ull a2 = ffma2v(pack2(cf.x, cf.y), negK2, lvm2);  // c*(-K2C)+(lv-M)
            float2 af = unpack2(a2);
            ull e2 = pack2(ex2f(af.x), ex2f(af.y));
            fadd2(s2, e2);
        }
    }
    float2 sf = unpack2(s2);
    float s = sf.x + sf.y;
#pragma unroll
    for (int o = 16; o; o >>= 1) s += __shfl_xor_sync(0xffffffffu, s, o);
    s = fmaxf(s, 1e-37f);
    return M + lg2f(s);
}

// Fused transport (final col pass), stale-shift. Returns t/s on ALL lanes.
static __device__ __forceinline__ float warp_line_transport_shift(const uint4* __restrict__ line,
                                                                  const float2* __restrict__ slv2,
                                                                  int lane, float M) {
    uint4 q[4];
#pragma unroll
    for (int t = 0; t < 4; t++) q[t] = line[lane + 32 * t];
    const ull negM2 = pack2(-M, -M);
    const ull negK2 = pack2(-K2C, -K2C);
    ull s2 = 0ull, t2 = 0ull;
#pragma unroll
    for (int t = 0; t < 4; t++) {
        int ci = lane + 32 * t;
        const __half2* hp = (const __half2*)&q[t];
#pragma unroll
        for (int e = 0; e < 4; e++) {
            float2 lv = slv2[e * 128 + ci];
            float2 cf = __half22float2(hp[e]);
            ull lvm2 = pack2(lv.x, lv.y);
            fadd2(lvm2, negM2);
            ull c2 = pack2(cf.x, cf.y);
            ull a2 = ffma2v(c2, negK2, lvm2);
            float2 af = unpack2(a2);
            ull e2 = pack2(ex2f(af.x), ex2f(af.y));
            fadd2(s2, e2);
            ffma2(t2, e2, c2);                        // t2 += e2 * c
        }
    }
    float2 sf = unpack2(s2);
    float2 tf = unpack2(t2);
    float s = sf.x + sf.y;
    float tt = tf.x + tf.y;
#pragma unroll
    for (int o = 16; o; o >>= 1) {
        s  += __shfl_xor_sync(0xffffffffu, s, o);
        tt += __shfl_xor_sync(0xffffffffu, tt, o);
    }
    s = fmaxf(s, 1e-37f);
    return tt / s;
}

// ---------------------------------------------------------------------------
// Kernel 3: persistent Sinkhorn.
// ---------------------------------------------------------------------------
__global__ __launch_bounds__(NTHR, 4) void sinkhorn_persist(float* __restrict__ out) {
    __shared__ __align__(16) float2 slv2[512];
    __shared__ float smx[256];
    __shared__ float wsum[8];

    int tid = threadIdx.x;
    int w = tid >> 5;
    int lane = tid & 31;
    int b = blockIdx.x >> 5;
    int lbase = (blockIdx.x & 31) * 32;
    const float* lvb = g_lv + (b << 10);
    const float* lub = g_lu + (b << 10);

    float lseu[4], lsev[4];

    for (int it = 0; it < 50; ++it) {
        stage_vec(slv2, lvb);
        __syncthreads();
#pragma unroll 1
        for (int k = 0; k < 4; ++k) {
            int row = (b << 10) + lbase + w * 4 + k;
            const uint4* line = (const uint4*)(g_ch + ((size_t)row << 10));
            float lse = (it == 0) ? warp_line_lse_exact(line, slv2, lane)
                                  : warp_line_lse_shift(line, slv2, lane, lseu[k]);
            lseu[k] = lse;
            if (lane == 0) g_lu[row] = -10.f - lse;
        }
        grid_barrier();
        if (it < 49) {
            stage_vec(slv2, lub);
            __syncthreads();
#pragma unroll 1
            for (int k = 0; k < 4; ++k) {
                int col = (b << 10) + lbase + w * 4 + k;
                const uint4* line = (const uint4*)(g_ct + ((size_t)col << 10));
                float lse = (it == 0) ? warp_line_lse_exact(line, slv2, lane)
                                      : warp_line_lse_shift(line, slv2, lane, lsev[k]);
                lsev[k] = lse;
                if (lane == 0) g_lv[col] = -10.f - lse;
            }
            grid_barrier();
        }
    }

    // 50th col pass fused with transport
    {
        stage_vec(slv2, lub);
        __syncthreads();
        float s = 0.f;
#pragma unroll 1
        for (int k = 0; k < 4; ++k) {
            int col = (b << 10) + lbase + w * 4 + k;
            const uint4* line = (const uint4*)(g_ct + ((size_t)col << 10));
            s += warp_line_transport_shift(line, slv2, lane, lsev[k]);
        }
        if (lane == 0) wsum[w] = s;
        __syncthreads();
        if (tid == 0) {
            float t = 0.f;
#pragma unroll
            for (int i = 0; i < 8; i++) t += wsum[i];
            g_part[blockIdx.x] = t;
        }
    }
    grid_barrier();

    if (blockIdx.x == 0) {
        float s = 0.f;
        for (int i = tid; i < NBLK; i += 256) s += __ldcg(&g_part[i]);
        smx[tid] = s;
        __syncthreads();
        for (int o = 128; o; o >>= 1) {
            if (tid < o) smx[tid] += smx[tid + o];
            __syncthreads();
        }
        if (tid == 0) out[0] = smx[0] * (1.f / (1024.f * 16.f));
    }
}

// ---------------------------------------------------------------------------
extern "C" void kernel_launch(void* const* d_in, const int* in_sizes, int n_in,
                              void* d_out, int out_size) {
    const float* x = (const float*)d_in[0];
    const float* y = (const float*)d_in[1];
    float* out = (float*)d_out;

    sumsq_kernel<<<4096, 256>>>(x, y);
    cost_kernel<<<dim3(8, 8, 16), 256>>>(x, y);
    sinkhorn_persist<<<NBLK, NTHR>>>(out);
}